// round 8
// baseline (speedup 1.0000x reference)
#include <cuda_runtime.h>
#include <cuda_fp16.h>
#include <cstdint>

// ============================================================
// TopKRouter, warp-specialized HMMA fp16 2-split pipeline v3:
//   logits = x @ W^T + b ; top-2 ; softmax(top2)
// M_CTA=128, 384 threads: warps 0-7 MMA consumers (32x32),
// warps 8-11 producers. 4-stage smem ring.
// v3: pass-major MMA order (no acc RAW stalls) + kk fragment
//     double-buffer + early empty-arrive.
// ============================================================

#define D_DIM  2048
#define NEXP   64
#define M_CTA  128
#define NCH    32
#define NSTG   4
#define NTHREADS 384

#define AB       16384
#define WB       8192
#define STGSZ    49152
#define STG(s)   (1024 + (s) * STGSZ)
#define SMEM_TOTAL (1024 + NSTG * STGSZ)   // 197632
#define LG_OFF   1024
#define LGS      65
#define SW16(row, c) ((row) * 128 + ((((c) ^ ((row) & 7))) << 4))

__device__ __align__(16) __half w0g[NEXP * D_DIM];
__device__ __align__(16) __half w1g[NEXP * D_DIM];

__global__ void wconv(const float* __restrict__ W) {
    int i = blockIdx.x * blockDim.x + threadIdx.x;
    float w = W[i];
    __half h0 = __float2half_rn(w);
    float  r  = w - __half2float(h0);
    w0g[i] = h0;
    w1g[i] = __float2half_rn(r * 2048.0f);
}

// ---------------- asm helpers ----------------
__device__ __forceinline__ uint32_t smem_u32(const void* p) {
    uint32_t a;
    asm("{ .reg .u64 t; cvta.to.shared.u64 t, %1; cvt.u32.u64 %0, t; }"
        : "=r"(a) : "l"(p));
    return a;
}
__device__ __forceinline__ void ldsm4(uint32_t* r, uint32_t addr) {
    asm volatile("ldmatrix.sync.aligned.m8n8.x4.shared.b16 {%0,%1,%2,%3}, [%4];"
                 : "=r"(r[0]), "=r"(r[1]), "=r"(r[2]), "=r"(r[3]) : "r"(addr));
}
__device__ __forceinline__ void mma16816(float* d, const uint32_t* a, const uint32_t* b) {
    asm volatile("mma.sync.aligned.m16n8k16.row.col.f32.f16.f16.f32 "
                 "{%0,%1,%2,%3}, {%4,%5,%6,%7}, {%8,%9}, {%0,%1,%2,%3};"
                 : "+f"(d[0]), "+f"(d[1]), "+f"(d[2]), "+f"(d[3])
                 : "r"(a[0]), "r"(a[1]), "r"(a[2]), "r"(a[3]), "r"(b[0]), "r"(b[1]));
}
__device__ __forceinline__ void cp16(uint32_t saddr, const void* gaddr) {
    asm volatile("cp.async.cg.shared.global [%0], [%1], 16;" :: "r"(saddr), "l"(gaddr));
}
#define MBAR_INIT(a, c) \
    asm volatile("mbarrier.init.shared.b64 [%0], %1;" :: "r"(a), "r"(c) : "memory")
#define MBAR_ARRIVE(a) \
    asm volatile("mbarrier.arrive.release.cta.shared::cta.b64 _, [%0];" :: "r"(a) : "memory")
#define CP_MBAR_ARRIVE(a) \
    asm volatile("cp.async.mbarrier.arrive.noinc.shared.b64 [%0];" :: "r"(a) : "memory")
#define MBAR_WAIT(addr, ph) do { \
    asm volatile("{\n\t.reg .pred P;\n\tWLP_%=:\n\t" \
        "mbarrier.try_wait.parity.acquire.cta.shared::cta.b64 P, [%0], %1, 0x989680;\n\t" \
        "@!P bra WLP_%=;\n\t}" :: "r"(addr), "r"(ph) : "memory"); \
} while (0)
#define STS128(addr, v) \
    asm volatile("st.shared.v4.b32 [%0], {%1,%2,%3,%4};" \
                 :: "r"(addr), "r"((v).x), "r"((v).y), "r"((v).z), "r"((v).w) : "memory")

__device__ __forceinline__ uint32_t cvt2(float u, float v, uint32_t& h1) {
    __half2 a = __float22half2_rn(make_float2(u, v));
    float2 f  = __half22float2(a);
    __half2 r = __float22half2_rn(make_float2(u - f.x, v - f.y));
    h1 = *reinterpret_cast<uint32_t*>(&r);
    return *reinterpret_cast<uint32_t*>(&a);
}

// ---------------- main kernel ----------------
__global__ __launch_bounds__(NTHREADS)
void router_main(const float* __restrict__ x, const float* __restrict__ b,
                 float* __restrict__ out, int n_tokens)
{
    extern __shared__ __align__(1024) char smem[];
    const uint32_t sb = smem_u32(smem);
    const int tid  = threadIdx.x;
    const int lane = tid & 31;
    const int tok0 = blockIdx.x * M_CTA;

    if (tid == 0) {
#pragma unroll
        for (int s = 0; s < NSTG; s++) {
            MBAR_INIT(sb + 512 + s * 16, 256);      // 128 STS-arr + 128 cp-arr
            MBAR_INIT(sb + 512 + s * 16 + 8, 256);  // 256 consumer arrivals
        }
    }
    if (tid < NEXP) reinterpret_cast<float*>(smem)[tid] = b[tid];
    __syncthreads();

    if (tid >= 256) {
        // ================= PRODUCER (warps 8-11) =================
        const int pt   = tid - 256;
        const int row  = pt;
        const int wrow = pt & 63;
        const int wsp  = pt >> 6;
        const float4* xp = reinterpret_cast<const float4*>(x)
                           + (size_t)(tok0 + row) * (D_DIM / 4);
        const char* wg = reinterpret_cast<const char*>(wsp ? w1g : w0g)
                         + wrow * (D_DIM * 2);
        const uint32_t wdst_off = 32768 + wsp * WB;

        uint32_t asw[8], wsw[8];
#pragma unroll
        for (int q = 0; q < 8; q++) asw[q] = SW16(row, q);
#pragma unroll
        for (int c = 0; c < 8; c++) wsw[c] = SW16(wrow, c);

        float4 xv[16];
#pragma unroll
        for (int i = 0; i < 16; i++) xv[i] = xp[i];

        int s = 0, ph = 1;
        for (int ch = 0; ch < NCH; ch++) {
            const uint32_t fullb  = sb + 512 + s * 16;
            const uint32_t emptyb = fullb + 8;
            MBAR_WAIT(emptyb, ph);
            const uint32_t stg = sb + STG(s);

#pragma unroll
            for (int c = 0; c < 8; c++)
                cp16(stg + wdst_off + wsw[c], wg + ch * 128 + c * 16);

#pragma unroll
            for (int q = 0; q < 8; q++) {
                float4 a = xv[2 * q], c = xv[2 * q + 1];
                uint4 h0q, h1q;
                h0q.x = cvt2(a.x, a.y, h1q.x);
                h0q.y = cvt2(a.z, a.w, h1q.y);
                h0q.z = cvt2(c.x, c.y, h1q.z);
                h0q.w = cvt2(c.z, c.w, h1q.w);
                STS128(stg + asw[q], h0q);
                STS128(stg + AB + asw[q], h1q);
            }
            CP_MBAR_ARRIVE(fullb);
            MBAR_ARRIVE(fullb);

            if (ch + 1 < NCH) {
#pragma unroll
                for (int i = 0; i < 16; i++) xv[i] = xp[(ch + 1) * 16 + i];
            }
            if (++s == NSTG) { s = 0; ph ^= 1; }
        }
        return;
    }

    // ================= CONSUMER (warps 0-7, 32x32 tiles) =================
    const int wid = tid >> 5;
    const int m0  = (wid & 3) * 32;
    const int n0  = (wid >> 2) * 32;

    float acc0[2][4][4], acc1[2][4][4];
#pragma unroll
    for (int mi = 0; mi < 2; mi++)
#pragma unroll
        for (int ng = 0; ng < 4; ng++)
#pragma unroll
            for (int q = 0; q < 4; q++) { acc0[mi][ng][q] = 0.f; acc1[mi][ng][q] = 0.f; }

    const int rowA  = m0 + (lane & 15);
    const int cAoff = lane >> 4;
    const int rowB  = n0 + (lane & 7) + ((lane >> 4) << 3);
    const int cBoff = (lane >> 3) & 1;

    // double-buffered fragments across kk
    uint32_t a0f[2][2][4], a1f[2][2][4], b0f[2][2][4], b1f[2][2][4];

#define LOAD_FRAGS(bb, kkv) do {                                       \
        const int cA_ = (kkv) * 2 + cAoff;                             \
        const int cB_ = (kkv) * 2 + cBoff;                             \
        _Pragma("unroll")                                              \
        for (int mi = 0; mi < 2; mi++) {                               \
            uint32_t ad = stg + SW16(rowA + mi * 16, cA_);             \
            ldsm4(a0f[bb][mi], ad);                                    \
            ldsm4(a1f[bb][mi], ad + AB);                               \
        }                                                              \
        _Pragma("unroll")                                              \
        for (int ni = 0; ni < 2; ni++) {                               \
            uint32_t bd = stg + 32768 + SW16(rowB + ni * 16, cB_);     \
            ldsm4(b0f[bb][ni], bd);                                    \
            ldsm4(b1f[bb][ni], bd + WB);                               \
        }                                                              \
    } while (0)

// pass-major MMA order: same accumulator reused at distance 8 -> no RAW stall
#define MMA_BLOCK(bb) do {                                             \
        _Pragma("unroll")                                              \
        for (int mi = 0; mi < 2; mi++)                                 \
        _Pragma("unroll")                                              \
        for (int ng = 0; ng < 4; ng++)                                 \
            mma16816(acc0[mi][ng], a0f[bb][mi],                        \
                     &b0f[bb][ng >> 1][(ng & 1) * 2]);                 \
        _Pragma("unroll")                                              \
        for (int mi = 0; mi < 2; mi++)                                 \
        _Pragma("unroll")                                              \
        for (int ng = 0; ng < 4; ng++)                                 \
            mma16816(acc0[mi][ng], a1f[bb][mi],                        \
                     &b0f[bb][ng >> 1][(ng & 1) * 2]);                 \
        _Pragma("unroll")                                              \
        for (int mi = 0; mi < 2; mi++)                                 \
        _Pragma("unroll")                                              \
        for (int ng = 0; ng < 4; ng++)                                 \
            mma16816(acc1[mi][ng], a0f[bb][mi],                        \
                     &b1f[bb][ng >> 1][(ng & 1) * 2]);                 \
    } while (0)

    int s = 0, ph = 0;
    for (int ch = 0; ch < NCH; ch++) {
        const uint32_t fullb  = sb + 512 + s * 16;
        const uint32_t emptyb = fullb + 8;
        MBAR_WAIT(fullb, ph);
        const uint32_t stg = sb + STG(s);

        LOAD_FRAGS(0, 0);
#pragma unroll
        for (int kk = 0; kk < 4; kk++) {
            const int cur = kk & 1;
            if (kk < 3) LOAD_FRAGS(cur ^ 1, kk + 1);
            else        MBAR_ARRIVE(emptyb);   // all stage reads issued (release)
            MMA_BLOCK(cur);
        }
        if (++s == NSTG) { s = 0; ph ^= 1; }
    }

    // consumers must finish reading stage 0 before logits overwrite it
    asm volatile("bar.sync 1, 256;" ::: "memory");

    float* lg = reinterpret_cast<float*>(smem + LG_OFF);
    const float S = 4.8828125e-4f;  // 2^-11
#pragma unroll
    for (int mi = 0; mi < 2; mi++) {
#pragma unroll
        for (int ng = 0; ng < 4; ng++) {
            int row = m0 + mi * 16 + (lane >> 2);
            int col = n0 + ng * 8 + 2 * (lane & 3);
            lg[row * LGS + col]           = acc0[mi][ng][0] + S * acc1[mi][ng][0];
            lg[row * LGS + col + 1]       = acc0[mi][ng][1] + S * acc1[mi][ng][1];
            lg[(row + 8) * LGS + col]     = acc0[mi][ng][2] + S * acc1[mi][ng][2];
            lg[(row + 8) * LGS + col + 1] = acc0[mi][ng][3] + S * acc1[mi][ng][3];
        }
    }
    asm volatile("bar.sync 1, 256;" ::: "memory");

    if (tid < M_CTA) {
        const float* row = &lg[tid * LGS];
        const float* bs  = reinterpret_cast<const float*>(smem);
        float v1 = -3.402823466e+38f, v2 = -3.402823466e+38f;
        int i1 = 0, i2 = 0;
#pragma unroll
        for (int e = 0; e < NEXP; e++) {
            float v = row[e] + bs[e];
            if (v > v1)      { v2 = v1; i2 = i1; v1 = v; i1 = e; }
            else if (v > v2) { v2 = v;  i2 = e; }
        }
        float e2  = expf(v2 - v1);
        float inv = 1.0f / (1.0f + e2);
        const int g = tok0 + tid;
        out[2 * g + 0] = inv;
        out[2 * g + 1] = e2 * inv;
        out[2 * n_tokens + 2 * g + 0] = (float)i1;
        out[2 * n_tokens + 2 * g + 1] = (float)i2;
    }
}

// ---------------- launch ----------------
extern "C" void kernel_launch(void* const* d_in, const int* in_sizes, int n_in,
                              void* d_out, int out_size)
{
    const float* x = (const float*)d_in[0];
    const float* W = (const float*)d_in[1];
    const float* b = (const float*)d_in[2];
    float* out = (float*)d_out;

    const int n_tokens = in_sizes[0] / D_DIM;   // 16384
    const int grid = n_tokens / M_CTA;          // 128

    cudaFuncSetAttribute(router_main, cudaFuncAttributeMaxDynamicSharedMemorySize, SMEM_TOTAL);

    wconv<<<NEXP * D_DIM / 256, 256>>>(W);
    router_main<<<grid, NTHREADS, SMEM_TOTAL>>>(x, b, out, n_tokens);
}